// round 6
// baseline (speedup 1.0000x reference)
#include <cuda_runtime.h>
#include <math.h>

#define NMAX 10000
#define EMAX 160000
#define TBL 16384
typedef unsigned long long ull;

// device scratch (no runtime allocation)
__device__ __align__(16) float g_p0[NMAX * 16];
__device__ __align__(16) float g_p1[NMAX * 24];
__device__ float g_z[NMAX];
__device__ float g_expv[EMAX];
__device__ __align__(16) float g_WkT[9216];      // [j*16+c]
__device__ __align__(16) float g_WvT[9216];
__device__ __align__(16) float g_tk[TBL * 16];   // hk(d) table
__device__ __align__(16) float g_tv[TBL * 16];   // hv(d) table
// per-node precomputed contractions
__device__ __align__(16) float g_D1k[NMAX * 256]; // [n][u][c] = sum_w p0_w Wk2[c,u*16+w]
__device__ __align__(16) float g_D4k[NMAX * 128]; // [n][u][c] = sum_w p0_w Wk2[c,448+u*16+w]
__device__ __align__(16) float g_S1v[NMAX * 256]; // [n][w][c] = sum_u x0_u Wv2[c,u*16+w]
__device__ __align__(16) float g_S2v[NMAX * 128]; // [n][w][c] = sum_u x0_u Wv2[c,256+u*8+w]

// ---------- packed f32x2 primitives ----------
__device__ __forceinline__ ull pk2(float a) {
    ull r; asm("mov.b64 %0, {%1,%1};" : "=l"(r) : "f"(a)); return r;
}
__device__ __forceinline__ ull pk(float a, float b) {
    ull r; asm("mov.b64 %0, {%1,%2};" : "=l"(r) : "f"(a), "f"(b)); return r;
}
__device__ __forceinline__ float2 upk(ull a) {
    float2 f; asm("mov.b64 {%0,%1}, %2;" : "=f"(f.x), "=f"(f.y) : "l"(a)); return f;
}
__device__ __forceinline__ ull f2fma(ull a, ull b, ull c) {
    ull d; asm("fma.rn.f32x2 %0, %1, %2, %3;" : "=l"(d) : "l"(a), "l"(b), "l"(c)); return d;
}
__device__ __forceinline__ ull f2mul(ull a, ull b) {
    ull d; asm("mul.rn.f32x2 %0, %1, %2;" : "=l"(d) : "l"(a), "l"(b)); return d;
}
__device__ __forceinline__ ull f2add(ull a, ull b) {
    ull d; asm("add.rn.f32x2 %0, %1, %2;" : "=l"(d) : "l"(a), "l"(b)); return d;
}

// shared col (16 floats) loaded once, FMA into THREE edges' accumulators
__device__ __forceinline__ void colfma8_3(ull A[8], ull B[8], ull C[8],
                                          const ulonglong2* __restrict__ c,
                                          ull fa, ull fb, ull fc) {
    ulonglong2 c0 = c[0], c1 = c[1], c2 = c[2], c3 = c[3];
    A[0] = f2fma(fa, c0.x, A[0]); B[0] = f2fma(fb, c0.x, B[0]); C[0] = f2fma(fc, c0.x, C[0]);
    A[1] = f2fma(fa, c0.y, A[1]); B[1] = f2fma(fb, c0.y, B[1]); C[1] = f2fma(fc, c0.y, C[1]);
    A[2] = f2fma(fa, c1.x, A[2]); B[2] = f2fma(fb, c1.x, B[2]); C[2] = f2fma(fc, c1.x, C[2]);
    A[3] = f2fma(fa, c1.y, A[3]); B[3] = f2fma(fb, c1.y, B[3]); C[3] = f2fma(fc, c1.y, C[3]);
    A[4] = f2fma(fa, c2.x, A[4]); B[4] = f2fma(fb, c2.x, B[4]); C[4] = f2fma(fc, c2.x, C[4]);
    A[5] = f2fma(fa, c2.y, A[5]); B[5] = f2fma(fb, c2.y, B[5]); C[5] = f2fma(fc, c2.y, C[5]);
    A[6] = f2fma(fa, c3.x, A[6]); B[6] = f2fma(fb, c3.x, B[6]); C[6] = f2fma(fc, c3.x, C[6]);
    A[7] = f2fma(fa, c3.y, A[7]); B[7] = f2fma(fb, c3.y, B[7]); C[7] = f2fma(fc, c3.y, C[7]);
}
// same for TWO edges
__device__ __forceinline__ void colfma8_2(ull A[8], ull B[8],
                                          const ulonglong2* __restrict__ c,
                                          ull fa, ull fb) {
    ulonglong2 c0 = c[0], c1 = c[1], c2 = c[2], c3 = c[3];
    A[0] = f2fma(fa, c0.x, A[0]); B[0] = f2fma(fb, c0.x, B[0]);
    A[1] = f2fma(fa, c0.y, A[1]); B[1] = f2fma(fb, c0.y, B[1]);
    A[2] = f2fma(fa, c1.x, A[2]); B[2] = f2fma(fb, c1.x, B[2]);
    A[3] = f2fma(fa, c1.y, A[3]); B[3] = f2fma(fb, c1.y, B[3]);
    A[4] = f2fma(fa, c2.x, A[4]); B[4] = f2fma(fb, c2.x, B[4]);
    A[5] = f2fma(fa, c2.y, A[5]); B[5] = f2fma(fb, c2.y, B[5]);
    A[6] = f2fma(fa, c3.x, A[6]); B[6] = f2fma(fb, c3.x, B[6]);
    A[7] = f2fma(fa, c3.y, A[7]); B[7] = f2fma(fb, c3.y, B[7]);
}
// stream a 16-float global row: acc += f * row
__device__ __forceinline__ void rowfma8(ull T[8], const float* __restrict__ gp, ull f) {
    const ulonglong2* c = reinterpret_cast<const ulonglong2*>(gp);
    ulonglong2 c0 = c[0], c1 = c[1], c2 = c[2], c3 = c[3];
    T[0] = f2fma(f, c0.x, T[0]); T[1] = f2fma(f, c0.y, T[1]);
    T[2] = f2fma(f, c1.x, T[2]); T[3] = f2fma(f, c1.y, T[3]);
    T[4] = f2fma(f, c2.x, T[4]); T[5] = f2fma(f, c2.y, T[5]);
    T[6] = f2fma(f, c3.x, T[6]); T[7] = f2fma(f, c3.y, T[7]);
}
// init acc = f * row (global)
__device__ __forceinline__ void rowmul8(ull T[8], const float* __restrict__ gp, ull f) {
    const ulonglong2* c = reinterpret_cast<const ulonglong2*>(gp);
    ulonglong2 c0 = c[0], c1 = c[1], c2 = c[2], c3 = c[3];
    T[0] = f2mul(f, c0.x); T[1] = f2mul(f, c0.y);
    T[2] = f2mul(f, c1.x); T[3] = f2mul(f, c1.y);
    T[4] = f2mul(f, c2.x); T[5] = f2mul(f, c2.y);
    T[6] = f2mul(f, c3.x); T[7] = f2mul(f, c3.y);
}
__device__ __forceinline__ ull dot8p(const ull h[8], const ull T[8]) {
    ull s0 = f2mul(h[0], T[0]);
    ull s1 = f2mul(h[1], T[1]);
    s0 = f2fma(h[2], T[2], s0); s1 = f2fma(h[3], T[3], s1);
    s0 = f2fma(h[4], T[4], s0); s1 = f2fma(h[5], T[5], s1);
    s0 = f2fma(h[6], T[6], s0); s1 = f2fma(h[7], T[7], s1);
    return f2add(s0, s1);
}
// dot of h with a global 16-float row
__device__ __forceinline__ float dotrow(const ull h[8], const float* __restrict__ gp) {
    const ulonglong2* c = reinterpret_cast<const ulonglong2*>(gp);
    ulonglong2 c0 = c[0], c1 = c[1], c2 = c[2], c3 = c[3];
    ull s0 = f2mul(h[0], c0.x);
    ull s1 = f2mul(h[1], c0.y);
    s0 = f2fma(h[2], c1.x, s0); s1 = f2fma(h[3], c1.y, s1);
    s0 = f2fma(h[4], c2.x, s0); s1 = f2fma(h[5], c2.y, s1);
    s0 = f2fma(h[6], c3.x, s0); s1 = f2fma(h[7], c3.y, s1);
    float2 r = upk(f2add(s0, s1));
    return r.x + r.y;
}
// two coldots sharing one smem column load
__device__ __forceinline__ void coldot2(const ull hA[8], const ull hB[8],
                                        const ulonglong2* __restrict__ c,
                                        float& oA, float& oB) {
    ulonglong2 c0 = c[0], c1 = c[1], c2 = c[2], c3 = c[3];
    ull a0 = f2mul(hA[0], c0.x), a1 = f2mul(hA[1], c0.y);
    ull b0 = f2mul(hB[0], c0.x), b1 = f2mul(hB[1], c0.y);
    a0 = f2fma(hA[2], c1.x, a0); a1 = f2fma(hA[3], c1.y, a1);
    b0 = f2fma(hB[2], c1.x, b0); b1 = f2fma(hB[3], c1.y, b1);
    a0 = f2fma(hA[4], c2.x, a0); a1 = f2fma(hA[5], c2.y, a1);
    b0 = f2fma(hB[4], c2.x, b0); b1 = f2fma(hB[5], c2.y, b1);
    a0 = f2fma(hA[6], c3.x, a0); a1 = f2fma(hA[7], c3.y, a1);
    b0 = f2fma(hB[6], c3.x, b0); b1 = f2fma(hB[7], c3.y, b1);
    float2 ra = upk(f2add(a0, a1)); oA = ra.x + ra.y;
    float2 rb = upk(f2add(b0, b1)); oB = rb.x + rb.y;
}

__device__ __forceinline__ void ld16(float o[16], const float* __restrict__ p) {
    const float4* p4 = reinterpret_cast<const float4*>(p);
    float4 t0 = p4[0], t1 = p4[1], t2 = p4[2], t3 = p4[3];
    o[0] = t0.x; o[1] = t0.y; o[2] = t0.z; o[3] = t0.w;
    o[4] = t1.x; o[5] = t1.y; o[6] = t1.z; o[7] = t1.w;
    o[8] = t2.x; o[9] = t2.y; o[10] = t2.z; o[11] = t2.w;
    o[12] = t3.x; o[13] = t3.y; o[14] = t3.z; o[15] = t3.w;
}
__device__ __forceinline__ void ld24(float o[24], const float* __restrict__ p) {
    const float4* p4 = reinterpret_cast<const float4*>(p);
    #pragma unroll
    for (int k = 0; k < 6; ++k) {
        float4 t = p4[k];
        o[4 * k] = t.x; o[4 * k + 1] = t.y; o[4 * k + 2] = t.z; o[4 * k + 3] = t.w;
    }
}

// lerp 16-wide table row -> 8 packed regs
__device__ __forceinline__ void table_lerp(const float* __restrict__ tab, float d, ull h2[8]) {
    float uu = d * ((float)(TBL - 1) * 0.125f);
    int i0 = (int)uu;
    if (i0 < 0) i0 = 0;
    if (i0 > TBL - 2) i0 = TBL - 2;
    float f = uu - (float)i0;
    const float4* t0 = reinterpret_cast<const float4*>(tab + i0 * 16);
    #pragma unroll
    for (int k = 0; k < 4; ++k) {
        float4 A = t0[k], B = t0[k + 4];
        float h0 = fmaf(f, B.x - A.x, A.x);
        float h1 = fmaf(f, B.y - A.y, A.y);
        float h2v = fmaf(f, B.z - A.z, A.z);
        float h3 = fmaf(f, B.w - A.w, A.w);
        h2[2 * k] = pk(h0, h1);
        h2[2 * k + 1] = pk(h2v, h3);
    }
}

// -------- setup: weight transpose + radial MLP tables
__global__ void setup_kernel(const float* __restrict__ Wk2, const float* __restrict__ Wv2,
                             const float* __restrict__ Wk1, const float* __restrict__ Wv1) {
    int idx = blockIdx.x * 256 + threadIdx.x;
    if (idx < 9216) {
        g_WkT[idx] = Wk2[(idx & 15) * 576 + (idx >> 4)];
    } else if (idx < 18432) {
        int t = idx - 9216;
        g_WvT[t] = Wv2[(t & 15) * 576 + (t >> 4)];
    } else if (idx < 18432 + TBL) {
        int i = idx - 18432;
        float d = (float)i * (8.0f / (float)(TBL - 1));
        float emb[16];
        #pragma unroll
        for (int b = 0; b < 16; ++b) {
            float cb = 0.47058824f * (float)(b + 1);
            float diff = (d - cb) * 2.125f;
            float q = 1.0f - diff * diff;
            emb[b] = (q > 0.f) ? 33.7342930f * expf(-2.0f / q) : 0.f;
        }
        #pragma unroll
        for (int c = 0; c < 16; ++c) {
            float sk = 0.f, sv = 0.f;
            #pragma unroll
            for (int b = 0; b < 16; ++b) {
                sk = fmaf(emb[b], Wk1[b * 16 + c], sk);
                sv = fmaf(emb[b], Wv1[b * 16 + c], sv);
            }
            sk *= 0.25f; sv *= 0.25f;
            g_tk[i * 16 + c] = sk / (1.f + expf(-sk));
            g_tv[i * 16 + c] = sv / (1.f + expf(-sv));
        }
    }
}

// -------- per-node p0/p1 = x(WqWd) with norms folded; zero z and out
__global__ __launch_bounds__(128) void node_prep(
    const float* __restrict__ x,
    const float* __restrict__ Wq0, const float* __restrict__ Wq1,
    const float* __restrict__ Wd0, const float* __restrict__ Wd1,
    float* __restrict__ out, int n) {
    __shared__ float C0[256];
    __shared__ float C1[64];
    int t = threadIdx.x;
    for (int idx = t; idx < 256; idx += blockDim.x) {
        int u = idx >> 4, v = idx & 15;
        float s = 0.f;
        #pragma unroll
        for (int w = 0; w < 16; ++w) s = fmaf(Wq0[u * 16 + w], Wd0[w * 16 + v], s);
        C0[idx] = s * 0.25f;
    }
    if (t < 64) {
        int u = t >> 3, v = t & 7;
        float s = 0.f;
        #pragma unroll
        for (int w = 0; w < 8; ++w) s = fmaf(Wq1[u * 8 + w], Wd1[w * 8 + v], s);
        C1[t] = s * 0.2041241452f;  // 1/(sqrt(8)*sqrt(3))
    }
    __syncthreads();
    int i = blockIdx.x * blockDim.x + t;
    if (i >= n) return;

    float x0[16];
    #pragma unroll
    for (int u = 0; u < 16; ++u) x0[u] = x[i * 40 + u];
    #pragma unroll
    for (int v = 0; v < 16; ++v) {
        float s = 0.f;
        #pragma unroll
        for (int u = 0; u < 16; ++u) s = fmaf(x0[u], C0[u * 16 + v], s);
        g_p0[i * 16 + v] = s;
    }
    float x1[24];
    #pragma unroll
    for (int k = 0; k < 24; ++k) x1[k] = x[i * 40 + 16 + k];
    #pragma unroll
    for (int v = 0; v < 8; ++v) {
        #pragma unroll
        for (int c = 0; c < 3; ++c) {
            float s = 0.f;
            #pragma unroll
            for (int u = 0; u < 8; ++u) s = fmaf(x1[u * 3 + c], C1[u * 8 + v], s);
            g_p1[i * 24 + v * 3 + c] = s;
        }
    }
    g_z[i] = 0.f;
    float4 z4 = make_float4(0.f, 0.f, 0.f, 0.f);
    float4* o4 = reinterpret_cast<float4*>(out + i * 40);
    #pragma unroll
    for (int m = 0; m < 10; ++m) o4[m] = z4;
}

// -------- per-node contracted weight tables (needs p0 from node_prep)
// thread = (node, row): rows 0-15 D1k(u), 16-23 D4k(u), 24-39 S1v(w), 40-47 S2v(w)
__global__ __launch_bounds__(256) void node_tables(
    const float* __restrict__ x,
    const float* __restrict__ Wk2, const float* __restrict__ Wv2, int n) {
    int idx = blockIdx.x * 256 + threadIdx.x;
    int node = idx / 48;
    int row = idx % 48;
    if (node >= n) return;
    float o[16];
    if (row < 16) {           // D1k: sum_w p0_w Wk2[c, u*16+w]
        int u = row;
        float p[16]; ld16(p, g_p0 + node * 16);
        #pragma unroll
        for (int c = 0; c < 16; ++c) {
            const float* wr = Wk2 + c * 576 + u * 16;
            float s = 0.f;
            #pragma unroll
            for (int w = 0; w < 16; ++w) s = fmaf(p[w], wr[w], s);
            o[c] = s;
        }
        float4* dst = reinterpret_cast<float4*>(g_D1k + node * 256 + u * 16);
        const float4* src = reinterpret_cast<const float4*>(o);
        dst[0] = src[0]; dst[1] = src[1]; dst[2] = src[2]; dst[3] = src[3];
    } else if (row < 24) {    // D4k: sum_w p0_w Wk2[c, 448+u*16+w]
        int u = row - 16;
        float p[16]; ld16(p, g_p0 + node * 16);
        #pragma unroll
        for (int c = 0; c < 16; ++c) {
            const float* wr = Wk2 + c * 576 + 448 + u * 16;
            float s = 0.f;
            #pragma unroll
            for (int w = 0; w < 16; ++w) s = fmaf(p[w], wr[w], s);
            o[c] = s;
        }
        float4* dst = reinterpret_cast<float4*>(g_D4k + node * 128 + u * 16);
        const float4* src = reinterpret_cast<const float4*>(o);
        dst[0] = src[0]; dst[1] = src[1]; dst[2] = src[2]; dst[3] = src[3];
    } else if (row < 40) {    // S1v: sum_u x0_u Wv2[c, u*16+w]
        int w = row - 24;
        float xv[16]; ld16(xv, x + node * 40);
        #pragma unroll
        for (int c = 0; c < 16; ++c) {
            const float* wr = Wv2 + c * 576 + w;
            float s = 0.f;
            #pragma unroll
            for (int u = 0; u < 16; ++u) s = fmaf(xv[u], wr[u * 16], s);
            o[c] = s;
        }
        float4* dst = reinterpret_cast<float4*>(g_S1v + node * 256 + w * 16);
        const float4* src = reinterpret_cast<const float4*>(o);
        dst[0] = src[0]; dst[1] = src[1]; dst[2] = src[2]; dst[3] = src[3];
    } else {                  // S2v: sum_u x0_u Wv2[c, 256+u*8+w]
        int w = row - 40;
        float xv[16]; ld16(xv, x + node * 40);
        #pragma unroll
        for (int c = 0; c < 16; ++c) {
            const float* wr = Wv2 + c * 576 + 256 + w;
            float s = 0.f;
            #pragma unroll
            for (int u = 0; u < 16; ++u) s = fmaf(xv[u], wr[u * 8], s);
            o[c] = s;
        }
        float4* dst = reinterpret_cast<float4*>(g_S2v + node * 128 + w * 16);
        const float4* src = reinterpret_cast<const float4*>(o);
        dst[0] = src[0]; dst[1] = src[1]; dst[2] = src[2]; dst[3] = src[3];
    }
}

// -------- score kernel: THREE edges/thread; smem walk only B2+B3 (192 cols)
__global__ __launch_bounds__(128) void edge_score(
    const float* __restrict__ x, const int* __restrict__ ei,
    const float* __restrict__ ea, const float* __restrict__ amf, int E) {
    __shared__ __align__(16) float Wk[3072];   // cols 256..447, [j'*16+c]
    {
        float4* s4 = reinterpret_cast<float4*>(Wk);
        const float4* g4 = reinterpret_cast<const float4*>(g_WkT + 4096);
        for (int i = threadIdx.x; i < 768; i += 128) s4[i] = g4[i];
    }
    __syncthreads();
    const ulonglong2* WK = reinterpret_cast<const ulonglong2*>(Wk);

    int e0 = blockIdx.x * 384 + threadIdx.x;
    int ee[3]; bool vv[3]; int src[3], dst[3]; float4 sh[3]; float dv[3];
    #pragma unroll
    for (int i = 0; i < 3; ++i) {
        ee[i] = e0 + i * 128; vv[i] = ee[i] < E;
        int idx = vv[i] ? ee[i] : 0;
        src[i] = ei[idx]; dst[i] = ei[E + idx];
        sh[i] = reinterpret_cast<const float4*>(ea)[idx];
        dv[i] = amf[idx];
    }
    ull m[3][8];
    #pragma unroll
    for (int i = 0; i < 3; ++i)
        #pragma unroll
        for (int k = 0; k < 8; ++k) m[i][k] = pk2(0.f);

    // phase 1: x0 gather + D1k stream (B1 via dst table)
    float x0[3][16];
    #pragma unroll
    for (int i = 0; i < 3; ++i) ld16(x0[i], x + src[i] * 40);
    #pragma unroll 2
    for (int u = 0; u < 16; ++u) {
        #pragma unroll
        for (int i = 0; i < 3; ++i)
            rowfma8(m[i], g_D1k + dst[i] * 256 + u * 16, pk2(x0[i][u] * sh[i].x));
    }
    // r from p1[dst]
    float r[3][8];
    #pragma unroll
    for (int i = 0; i < 3; ++i) {
        float t[24]; ld24(t, g_p1 + dst[i] * 24);
        #pragma unroll
        for (int w = 0; w < 8; ++w)
            r[i][w] = t[3 * w] * sh[i].y + t[3 * w + 1] * sh[i].z + t[3 * w + 2] * sh[i].w;
    }
    // B2 walk: cols j' = u*8+w
    #pragma unroll 1
    for (int u = 0; u < 16; ++u) {
        #pragma unroll
        for (int w = 0; w < 8; ++w)
            colfma8_3(m[0], m[1], m[2], WK + (u * 8 + w) * 4,
                      pk2(x0[0][u] * r[0][w]), pk2(x0[1][u] * r[1][w]), pk2(x0[2][u] * r[2][w]));
    }
    // dd + D4k stream (B4 via dst table)
    {
        float dd[3][8];
        #pragma unroll
        for (int i = 0; i < 3; ++i) {
            float t[24]; ld24(t, x + src[i] * 40 + 16);
            #pragma unroll
            for (int u = 0; u < 8; ++u)
                dd[i][u] = (t[3 * u] * sh[i].y + t[3 * u + 1] * sh[i].z + t[3 * u + 2] * sh[i].w) * 0.57735027f;
        }
        #pragma unroll 2
        for (int u = 0; u < 8; ++u) {
            #pragma unroll
            for (int i = 0; i < 3; ++i)
                rowfma8(m[i], g_D4k + dst[i] * 128 + u * 16, pk2(dd[i][u]));
        }
    }
    // B3 walk: cols j' = 128+u*8+w, g = (x1*sh0)·p1[w]
    float x1s[3][24];
    #pragma unroll
    for (int i = 0; i < 3; ++i) {
        float t[24]; ld24(t, x + src[i] * 40 + 16);
        #pragma unroll
        for (int k = 0; k < 24; ++k) x1s[i][k] = t[k] * sh[i].x;
    }
    #pragma unroll 1
    for (int w = 0; w < 8; ++w) {
        float q[3][3];
        #pragma unroll
        for (int i = 0; i < 3; ++i) {
            const float* p = g_p1 + dst[i] * 24 + 3 * w;
            q[i][0] = p[0]; q[i][1] = p[1]; q[i][2] = p[2];
        }
        #pragma unroll
        for (int u = 0; u < 8; ++u) {
            colfma8_3(m[0], m[1], m[2], WK + (128 + u * 8 + w) * 4,
                pk2(x1s[0][3 * u] * q[0][0] + x1s[0][3 * u + 1] * q[0][1] + x1s[0][3 * u + 2] * q[0][2]),
                pk2(x1s[1][3 * u] * q[1][0] + x1s[1][3 * u + 1] * q[1][1] + x1s[1][3 * u + 2] * q[1][2]),
                pk2(x1s[2][3 * u] * q[2][0] + x1s[2][3 * u + 1] * q[2][1] + x1s[2][3 * u + 2] * q[2][2]));
        }
    }
    // finalize
    #pragma unroll
    for (int i = 0; i < 3; ++i) {
        ull hk[8];
        table_lerp(g_tk, dv[i], hk);
        float2 s2 = upk(dot8p(hk, m[i]));
        float score = (s2.x + s2.y) * 0.0028527222f;  // 1/(4*sqrt(24)*sqrt(320))
        float tc = 10.0f * (1.0f - dv[i] * 0.125f);
        float cut = (tc > 0.f) ? __expf(-__frcp_rn(tc)) : 0.f;
        float ev = cut * __expf(score);
        if (vv[i]) {
            g_expv[ee[i]] = ev;
            atomicAdd(&g_z[dst[i]], ev);
        }
    }
}

// -------- value kernel: TWO edges/thread; smem walk only B3+B4 (192 cols)
__global__ __launch_bounds__(128) void edge_value(
    const float* __restrict__ x, const int* __restrict__ ei,
    const float* __restrict__ ea, const float* __restrict__ amf,
    float* __restrict__ out, int E) {
    __shared__ __align__(16) float Wv[3072];   // cols 384..575: B3 j'=u*8+w, B4 j'=64+u*16+w
    {
        float4* s4 = reinterpret_cast<float4*>(Wv);
        const float4* g4 = reinterpret_cast<const float4*>(g_WvT + 6144);
        for (int i = threadIdx.x; i < 768; i += 128) s4[i] = g4[i];
    }
    __syncthreads();
    const ulonglong2* WV = reinterpret_cast<const ulonglong2*>(Wv);

    int e0 = blockIdx.x * 256 + threadIdx.x;
    int e1 = e0 + 128;
    bool v0 = e0 < E, v1 = e1 < E;
    int ia = v0 ? e0 : 0, ib = v1 ? e1 : 0;
    int srcA = ei[ia], dstA = ei[E + ia];
    int srcB = ei[ib], dstB = ei[E + ib];
    const float4 shA = reinterpret_cast<const float4*>(ea)[ia];
    const float4 shB = reinterpret_cast<const float4*>(ea)[ib];
    float dA = amf[ia], dB = amf[ib];
    float fsA = sqrtf(g_expv[ia]) * 0.0510310363f;
    float fsB = sqrtf(g_expv[ib]) * 0.0510310363f;

    ull hvA[8], hvB[8];
    table_lerp(g_tv, dA, hvA);
    table_lerp(g_tv, dB, hvB);

    // A-phase via S2v table: A[w] = hv . S2v[src][w]
    float AA[8], AB[8];
    #pragma unroll
    for (int w = 0; w < 8; ++w) {
        AA[w] = dotrow(hvA, g_S2v + srcA * 128 + w * 16);
        AB[w] = dotrow(hvB, g_S2v + srcB * 128 + w * 16);
    }
    // dd from x1
    float ddA[8], ddB[8];
    {
        float tA[24], tB[24];
        ld24(tA, x + srcA * 40 + 16); ld24(tB, x + srcB * 40 + 16);
        #pragma unroll
        for (int u = 0; u < 8; ++u) {
            ddA[u] = (tA[3 * u] * shA.y + tA[3 * u + 1] * shA.z + tA[3 * u + 2] * shA.w) * 0.57735027f;
            ddB[u] = (tB[3 * u] * shB.y + tB[3 * u + 1] * shB.z + tB[3 * u + 2] * shB.w) * 0.57735027f;
        }
    }
    float* obA = out + dstA * 40;
    float* obB = out + dstB * 40;

    // o0[w] = hv . ( sh0*S1v[src][w] + sum_u dd_u W4col ), cols j' = 64+u*16+w
    #pragma unroll 1
    for (int w = 0; w < 16; ++w) {
        ull UA[8], UB[8];
        rowmul8(UA, g_S1v + srcA * 256 + w * 16, pk2(shA.x));
        rowmul8(UB, g_S1v + srcB * 256 + w * 16, pk2(shB.x));
        #pragma unroll
        for (int u = 0; u < 8; ++u)
            colfma8_2(UA, UB, WV + (64 + u * 16 + w) * 4, pk2(ddA[u]), pk2(ddB[u]));
        float2 sA = upk(dot8p(hvA, UA));
        float2 sB = upk(dot8p(hvB, UB));
        if (v0) atomicAdd(obA + w, (sA.x + sA.y) * fsA);
        if (v1) atomicAdd(obB + w, (sB.x + sB.y) * fsB);
    }
    // o1: x1s resident; per w: vxyz = A[w]*sh1 + sum_u (hv.W3col)*x1s[u,:]; cols j'=u*8+w
    float x1A[24], x1B[24];
    ld24(x1A, x + srcA * 40 + 16); ld24(x1B, x + srcB * 40 + 16);
    #pragma unroll
    for (int k = 0; k < 24; ++k) { x1A[k] *= shA.x; x1B[k] *= shB.x; }
    #pragma unroll 1
    for (int w = 0; w < 8; ++w) {
        float vxA = AA[w] * shA.y, vyA = AA[w] * shA.z, vzA = AA[w] * shA.w;
        float vxB = AB[w] * shB.y, vyB = AB[w] * shB.z, vzB = AB[w] * shB.w;
        #pragma unroll
        for (int u = 0; u < 8; ++u) {
            float sA_, sB_;
            coldot2(hvA, hvB, WV + (u * 8 + w) * 4, sA_, sB_);
            vxA = fmaf(sA_, x1A[3 * u], vxA);
            vyA = fmaf(sA_, x1A[3 * u + 1], vyA);
            vzA = fmaf(sA_, x1A[3 * u + 2], vzA);
            vxB = fmaf(sB_, x1B[3 * u], vxB);
            vyB = fmaf(sB_, x1B[3 * u + 1], vyB);
            vzB = fmaf(sB_, x1B[3 * u + 2], vzB);
        }
        if (v0) {
            atomicAdd(obA + 16 + 3 * w, vxA * fsA);
            atomicAdd(obA + 17 + 3 * w, vyA * fsA);
            atomicAdd(obA + 18 + 3 * w, vzA * fsA);
        }
        if (v1) {
            atomicAdd(obB + 16 + 3 * w, vxB * fsB);
            atomicAdd(obB + 17 + 3 * w, vyB * fsB);
            atomicAdd(obB + 18 + 3 * w, vzB * fsB);
        }
    }
}

// -------- epilogue: out[i] *= rsqrt(z[i])
__global__ void normalize(float* __restrict__ out, int n) {
    int i = blockIdx.x * 128 + threadIdx.x;
    if (i >= n) return;
    float zz = g_z[i];
    if (zz <= 0.f) zz = 1.f;
    float s = rsqrtf(zz);
    float4* o4 = reinterpret_cast<float4*>(out + i * 40);
    #pragma unroll
    for (int m = 0; m < 10; ++m) {
        float4 v = o4[m];
        v.x *= s; v.y *= s; v.z *= s; v.w *= s;
        o4[m] = v;
    }
}

extern "C" void kernel_launch(void* const* d_in, const int* in_sizes, int n_in,
                              void* d_out, int out_size) {
    const float* x   = (const float*)d_in[0];
    const int*   ei  = (const int*)d_in[1];
    const float* ea  = (const float*)d_in[2];
    const float* amf = (const float*)d_in[5];
    const float* Wq0 = (const float*)d_in[6];
    const float* Wq1 = (const float*)d_in[7];
    const float* Wk1 = (const float*)d_in[8];
    const float* Wk2 = (const float*)d_in[9];
    const float* Wv1 = (const float*)d_in[10];
    const float* Wv2 = (const float*)d_in[11];
    const float* Wd0 = (const float*)d_in[12];
    const float* Wd1 = (const float*)d_in[13];
    float* out = (float*)d_out;

    int n = in_sizes[0] / 40;
    int E = in_sizes[2] / 4;

    setup_kernel<<<(18432 + TBL + 255) / 256, 256>>>(Wk2, Wv2, Wk1, Wv1);
    node_prep<<<(n + 127) / 128, 128>>>(x, Wq0, Wq1, Wd0, Wd1, out, n);
    node_tables<<<(n * 48 + 255) / 256, 256>>>(x, Wk2, Wv2, n);
    edge_score<<<(E + 383) / 384, 128>>>(x, ei, ea, amf, E);
    edge_value<<<(E + 255) / 256, 128>>>(x, ei, ea, amf, out, E);
    normalize<<<(n + 127) / 128, 128>>>(out, n);
}

// round 7
// speedup vs baseline: 1.7609x; 1.7609x over previous
#include <cuda_runtime.h>
#include <math.h>

#define NMAX 10000
#define EMAX 160000
#define TBL 16384
typedef unsigned long long ull;

// device scratch (no runtime allocation)
__device__ __align__(16) float g_p0[NMAX * 16];
__device__ __align__(16) float g_p1[NMAX * 24];
__device__ float g_z[NMAX];
__device__ float g_expv[EMAX];
__device__ __align__(16) float g_WkT[9216];      // [j*16+c]
__device__ __align__(16) float g_WvT[9216];
__device__ __align__(16) float g_tk[TBL * 16];   // hk(d) table
__device__ __align__(16) float g_tv[TBL * 16];   // hv(d) table
// edge sort (by dst) scratch
__device__ int g_cnt[NMAX];
__device__ int g_off[NMAX];
__device__ int g_src[EMAX];
__device__ int g_dst[EMAX];
__device__ __align__(16) float4 g_sea[EMAX];
__device__ float g_sd[EMAX];

// ---------- packed f32x2 primitives ----------
__device__ __forceinline__ ull pk2(float a) {
    ull r; asm("mov.b64 %0, {%1,%1};" : "=l"(r) : "f"(a)); return r;
}
__device__ __forceinline__ ull pk(float a, float b) {
    ull r; asm("mov.b64 %0, {%1,%2};" : "=l"(r) : "f"(a), "f"(b)); return r;
}
__device__ __forceinline__ float2 upk(ull a) {
    float2 f; asm("mov.b64 {%0,%1}, %2;" : "=f"(f.x), "=f"(f.y) : "l"(a)); return f;
}
__device__ __forceinline__ ull f2fma(ull a, ull b, ull c) {
    ull d; asm("fma.rn.f32x2 %0, %1, %2, %3;" : "=l"(d) : "l"(a), "l"(b), "l"(c)); return d;
}
__device__ __forceinline__ ull f2mul(ull a, ull b) {
    ull d; asm("mul.rn.f32x2 %0, %1, %2;" : "=l"(d) : "l"(a), "l"(b)); return d;
}
__device__ __forceinline__ ull f2add(ull a, ull b) {
    ull d; asm("add.rn.f32x2 %0, %1, %2;" : "=l"(d) : "l"(a), "l"(b)); return d;
}

// shared col (16 floats) loaded once, FMA into edges' accumulators
__device__ __forceinline__ void colfma8_2(ull A[8], ull B[8],
                                          const ulonglong2* __restrict__ c,
                                          ull fa, ull fb) {
    ulonglong2 c0 = c[0], c1 = c[1], c2 = c[2], c3 = c[3];
    A[0] = f2fma(fa, c0.x, A[0]); B[0] = f2fma(fb, c0.x, B[0]);
    A[1] = f2fma(fa, c0.y, A[1]); B[1] = f2fma(fb, c0.y, B[1]);
    A[2] = f2fma(fa, c1.x, A[2]); B[2] = f2fma(fb, c1.x, B[2]);
    A[3] = f2fma(fa, c1.y, A[3]); B[3] = f2fma(fb, c1.y, B[3]);
    A[4] = f2fma(fa, c2.x, A[4]); B[4] = f2fma(fb, c2.x, B[4]);
    A[5] = f2fma(fa, c2.y, A[5]); B[5] = f2fma(fb, c2.y, B[5]);
    A[6] = f2fma(fa, c3.x, A[6]); B[6] = f2fma(fb, c3.x, B[6]);
    A[7] = f2fma(fa, c3.y, A[7]); B[7] = f2fma(fb, c3.y, B[7]);
}
__device__ __forceinline__ ull dot8p(const ull h[8], const ull T[8]) {
    ull s0 = f2mul(h[0], T[0]);
    ull s1 = f2mul(h[1], T[1]);
    s0 = f2fma(h[2], T[2], s0); s1 = f2fma(h[3], T[3], s1);
    s0 = f2fma(h[4], T[4], s0); s1 = f2fma(h[5], T[5], s1);
    s0 = f2fma(h[6], T[6], s0); s1 = f2fma(h[7], T[7], s1);
    return f2add(s0, s1);
}
// two coldots sharing one smem column load
__device__ __forceinline__ void coldot2(const ull hA[8], const ull hB[8],
                                        const ulonglong2* __restrict__ c,
                                        float& oA, float& oB) {
    ulonglong2 c0 = c[0], c1 = c[1], c2 = c[2], c3 = c[3];
    ull a0 = f2mul(hA[0], c0.x), a1 = f2mul(hA[1], c0.y);
    ull b0 = f2mul(hB[0], c0.x), b1 = f2mul(hB[1], c0.y);
    a0 = f2fma(hA[2], c1.x, a0); a1 = f2fma(hA[3], c1.y, a1);
    b0 = f2fma(hB[2], c1.x, b0); b1 = f2fma(hB[3], c1.y, b1);
    a0 = f2fma(hA[4], c2.x, a0); a1 = f2fma(hA[5], c2.y, a1);
    b0 = f2fma(hB[4], c2.x, b0); b1 = f2fma(hB[5], c2.y, b1);
    a0 = f2fma(hA[6], c3.x, a0); a1 = f2fma(hA[7], c3.y, a1);
    b0 = f2fma(hB[6], c3.x, b0); b1 = f2fma(hB[7], c3.y, b1);
    float2 ra = upk(f2add(a0, a1)); oA = ra.x + ra.y;
    float2 rb = upk(f2add(b0, b1)); oB = rb.x + rb.y;
}

__device__ __forceinline__ void ld16(float o[16], const float* __restrict__ p) {
    const float4* p4 = reinterpret_cast<const float4*>(p);
    float4 t0 = p4[0], t1 = p4[1], t2 = p4[2], t3 = p4[3];
    o[0] = t0.x; o[1] = t0.y; o[2] = t0.z; o[3] = t0.w;
    o[4] = t1.x; o[5] = t1.y; o[6] = t1.z; o[7] = t1.w;
    o[8] = t2.x; o[9] = t2.y; o[10] = t2.z; o[11] = t2.w;
    o[12] = t3.x; o[13] = t3.y; o[14] = t3.z; o[15] = t3.w;
}
__device__ __forceinline__ void ld24(float o[24], const float* __restrict__ p) {
    const float4* p4 = reinterpret_cast<const float4*>(p);
    #pragma unroll
    for (int k = 0; k < 6; ++k) {
        float4 t = p4[k];
        o[4 * k] = t.x; o[4 * k + 1] = t.y; o[4 * k + 2] = t.z; o[4 * k + 3] = t.w;
    }
}

// lerp 16-wide table row -> 8 packed regs
__device__ __forceinline__ void table_lerp(const float* __restrict__ tab, float d, ull h2[8]) {
    float uu = d * ((float)(TBL - 1) * 0.125f);
    int i0 = (int)uu;
    if (i0 < 0) i0 = 0;
    if (i0 > TBL - 2) i0 = TBL - 2;
    float f = uu - (float)i0;
    const float4* t0 = reinterpret_cast<const float4*>(tab + i0 * 16);
    #pragma unroll
    for (int k = 0; k < 4; ++k) {
        float4 A = t0[k], B = t0[k + 4];
        float h0 = fmaf(f, B.x - A.x, A.x);
        float h1 = fmaf(f, B.y - A.y, A.y);
        float h2v = fmaf(f, B.z - A.z, A.z);
        float h3 = fmaf(f, B.w - A.w, A.w);
        h2[2 * k] = pk(h0, h1);
        h2[2 * k + 1] = pk(h2v, h3);
    }
}

// -------- setup: weight transpose + radial MLP tables + zero hist
__global__ void setup_kernel(const float* __restrict__ Wk2, const float* __restrict__ Wv2,
                             const float* __restrict__ Wk1, const float* __restrict__ Wv1) {
    int idx = blockIdx.x * 256 + threadIdx.x;
    if (idx < 9216) {
        g_WkT[idx] = Wk2[(idx & 15) * 576 + (idx >> 4)];
    } else if (idx < 18432) {
        int t = idx - 9216;
        g_WvT[t] = Wv2[(t & 15) * 576 + (t >> 4)];
    } else if (idx < 18432 + TBL) {
        int i = idx - 18432;
        float d = (float)i * (8.0f / (float)(TBL - 1));
        float emb[16];
        #pragma unroll
        for (int b = 0; b < 16; ++b) {
            float cb = 0.47058824f * (float)(b + 1);
            float diff = (d - cb) * 2.125f;
            float q = 1.0f - diff * diff;
            emb[b] = (q > 0.f) ? 33.7342930f * expf(-2.0f / q) : 0.f;
        }
        #pragma unroll
        for (int c = 0; c < 16; ++c) {
            float sk = 0.f, sv = 0.f;
            #pragma unroll
            for (int b = 0; b < 16; ++b) {
                sk = fmaf(emb[b], Wk1[b * 16 + c], sk);
                sv = fmaf(emb[b], Wv1[b * 16 + c], sv);
            }
            sk *= 0.25f; sv *= 0.25f;
            g_tk[i * 16 + c] = sk / (1.f + expf(-sk));
            g_tv[i * 16 + c] = sv / (1.f + expf(-sv));
        }
    } else if (idx < 18432 + TBL + NMAX) {
        g_cnt[idx - 18432 - TBL] = 0;
    }
}

// -------- counting sort by dst: hist -> scan -> scatter(+reorder)
__global__ void hist_kernel(const int* __restrict__ ei, int E) {
    int e = blockIdx.x * 256 + threadIdx.x;
    if (e < E) atomicAdd(&g_cnt[ei[E + e]], 1);
}
__global__ __launch_bounds__(1024) void scan_kernel(int n) {
    __shared__ int part[1024];
    int t = threadIdx.x;
    int chunk = (n + 1023) / 1024;
    int base = t * chunk;
    int s = 0;
    for (int i = 0; i < chunk; ++i) {
        int j = base + i;
        if (j < n) s += g_cnt[j];
    }
    part[t] = s;
    __syncthreads();
    for (int off = 1; off < 1024; off <<= 1) {
        int v = (t >= off) ? part[t - off] : 0;
        __syncthreads();
        part[t] += v;
        __syncthreads();
    }
    int run = (t > 0) ? part[t - 1] : 0;
    for (int i = 0; i < chunk; ++i) {
        int j = base + i;
        if (j < n) {
            int c = g_cnt[j];
            g_off[j] = run;
            run += c;
        }
    }
}
__global__ void scatter_kernel(const int* __restrict__ ei, const float* __restrict__ ea,
                               const float* __restrict__ amf, int E) {
    int e = blockIdx.x * 256 + threadIdx.x;
    if (e >= E) return;
    int dst = ei[E + e];
    int pos = atomicAdd(&g_off[dst], 1);
    g_src[pos] = ei[e];
    g_dst[pos] = dst;
    g_sea[pos] = reinterpret_cast<const float4*>(ea)[e];
    g_sd[pos] = amf[e];
}

// -------- per-node p0/p1 = x(WqWd) with norms folded; zero z and out
__global__ __launch_bounds__(128) void node_prep(
    const float* __restrict__ x,
    const float* __restrict__ Wq0, const float* __restrict__ Wq1,
    const float* __restrict__ Wd0, const float* __restrict__ Wd1,
    float* __restrict__ out, int n) {
    __shared__ float C0[256];
    __shared__ float C1[64];
    int t = threadIdx.x;
    for (int idx = t; idx < 256; idx += blockDim.x) {
        int u = idx >> 4, v = idx & 15;
        float s = 0.f;
        #pragma unroll
        for (int w = 0; w < 16; ++w) s = fmaf(Wq0[u * 16 + w], Wd0[w * 16 + v], s);
        C0[idx] = s * 0.25f;
    }
    if (t < 64) {
        int u = t >> 3, v = t & 7;
        float s = 0.f;
        #pragma unroll
        for (int w = 0; w < 8; ++w) s = fmaf(Wq1[u * 8 + w], Wd1[w * 8 + v], s);
        C1[t] = s * 0.2041241452f;  // 1/(sqrt(8)*sqrt(3))
    }
    __syncthreads();
    int i = blockIdx.x * blockDim.x + t;
    if (i >= n) return;

    float x0[16];
    #pragma unroll
    for (int u = 0; u < 16; ++u) x0[u] = x[i * 40 + u];
    #pragma unroll
    for (int v = 0; v < 16; ++v) {
        float s = 0.f;
        #pragma unroll
        for (int u = 0; u < 16; ++u) s = fmaf(x0[u], C0[u * 16 + v], s);
        g_p0[i * 16 + v] = s;
    }
    float x1[24];
    #pragma unroll
    for (int k = 0; k < 24; ++k) x1[k] = x[i * 40 + 16 + k];
    #pragma unroll
    for (int v = 0; v < 8; ++v) {
        #pragma unroll
        for (int c = 0; c < 3; ++c) {
            float s = 0.f;
            #pragma unroll
            for (int u = 0; u < 8; ++u) s = fmaf(x1[u * 3 + c], C1[u * 8 + v], s);
            g_p1[i * 24 + v * 3 + c] = s;
        }
    }
    g_z[i] = 0.f;
    float4 z4 = make_float4(0.f, 0.f, 0.f, 0.f);
    float4* o4 = reinterpret_cast<float4*>(out + i * 40);
    #pragma unroll
    for (int m = 0; m < 10; ++m) o4[m] = z4;
}

// -------- score kernel: TWO edges per thread (dst-sorted), Wk column read once for both
__global__ __launch_bounds__(128) void edge_score(const float* __restrict__ x, int E) {
    __shared__ __align__(16) float Wk[9216];
    {
        float4* s4 = reinterpret_cast<float4*>(Wk);
        const float4* g4 = reinterpret_cast<const float4*>(g_WkT);
        for (int i = threadIdx.x; i < 2304; i += 128) s4[i] = g4[i];
    }
    __syncthreads();
    const ulonglong2* WK = reinterpret_cast<const ulonglong2*>(Wk);

    int e0 = blockIdx.x * 256 + threadIdx.x;
    int e1 = e0 + 128;
    bool v0 = e0 < E, v1 = e1 < E;
    int ia = v0 ? e0 : 0, ib = v1 ? e1 : 0;
    int srcA = g_src[ia], dstA = g_dst[ia];
    int srcB = g_src[ib], dstB = g_dst[ib];
    const float4 shA = g_sea[ia];
    const float4 shB = g_sea[ib];
    float dA = g_sd[ia], dB = g_sd[ib];

    float x0A[16], x0B[16], p0A[16], p0B[16];
    ld16(x0A, x + srcA * 40); ld16(x0B, x + srcB * 40);
    ld16(p0A, g_p0 + dstA * 16); ld16(p0B, g_p0 + dstB * 16);

    ull mA[8], mB[8];
    #pragma unroll
    for (int i = 0; i < 8; ++i) { mA[i] = pk2(0.f); mB[i] = pk2(0.f); }

    // block1: j=u*16+w, g = (x0[u]*sh0)*p0[w]
    #pragma unroll 1
    for (int u = 0; u < 16; ++u) {
        float aA = x0A[u] * shA.x, aB = x0B[u] * shB.x;
        #pragma unroll
        for (int w = 0; w < 16; ++w)
            colfma8_2(mA, mB, WK + (u * 16 + w) * 4, pk2(aA * p0A[w]), pk2(aB * p0B[w]));
    }
    // r from p1 (streamed, discarded)
    float rA[8], rB[8];
    {
        float tA[24], tB[24];
        ld24(tA, g_p1 + dstA * 24); ld24(tB, g_p1 + dstB * 24);
        #pragma unroll
        for (int w = 0; w < 8; ++w) {
            rA[w] = tA[3 * w] * shA.y + tA[3 * w + 1] * shA.z + tA[3 * w + 2] * shA.w;
            rB[w] = tB[3 * w] * shB.y + tB[3 * w + 1] * shB.z + tB[3 * w + 2] * shB.w;
        }
    }
    // block2: j=256+u*8+w, g = x0[u]*r[w]
    #pragma unroll 1
    for (int u = 0; u < 16; ++u) {
        float xA = x0A[u], xB = x0B[u];
        #pragma unroll
        for (int w = 0; w < 8; ++w)
            colfma8_2(mA, mB, WK + (256 + u * 8 + w) * 4, pk2(xA * rA[w]), pk2(xB * rB[w]));
    }
    // dd (x1 streamed, discarded)
    float ddA[8], ddB[8];
    {
        float tA[24], tB[24];
        ld24(tA, x + srcA * 40 + 16); ld24(tB, x + srcB * 40 + 16);
        #pragma unroll
        for (int u = 0; u < 8; ++u) {
            ddA[u] = (tA[3 * u] * shA.y + tA[3 * u + 1] * shA.z + tA[3 * u + 2] * shA.w) * 0.57735027f;
            ddB[u] = (tB[3 * u] * shB.y + tB[3 * u + 1] * shB.z + tB[3 * u + 2] * shB.w) * 0.57735027f;
        }
    }
    // block4: j=448+u*16+w, g = dd[u]*p0[w]
    #pragma unroll 1
    for (int u = 0; u < 8; ++u) {
        float aA = ddA[u], aB = ddB[u];
        #pragma unroll
        for (int w = 0; w < 16; ++w)
            colfma8_2(mA, mB, WK + (448 + u * 16 + w) * 4, pk2(aA * p0A[w]), pk2(aB * p0B[w]));
    }
    // block3: j=384+u*8+w, g = (x1*sh0)·p1[w]; x1 resident, p1 streamed per w
    float x1A[24], x1B[24];
    ld24(x1A, x + srcA * 40 + 16); ld24(x1B, x + srcB * 40 + 16);
    #pragma unroll
    for (int k = 0; k < 24; ++k) { x1A[k] *= shA.x; x1B[k] *= shB.x; }
    {
        const float* pA = g_p1 + dstA * 24;
        const float* pB = g_p1 + dstB * 24;
        #pragma unroll 1
        for (int w = 0; w < 8; ++w) {
            float qA0 = pA[3 * w], qA1 = pA[3 * w + 1], qA2 = pA[3 * w + 2];
            float qB0 = pB[3 * w], qB1 = pB[3 * w + 1], qB2 = pB[3 * w + 2];
            #pragma unroll
            for (int u = 0; u < 8; ++u) {
                float gA = x1A[3 * u] * qA0 + x1A[3 * u + 1] * qA1 + x1A[3 * u + 2] * qA2;
                float gB = x1B[3 * u] * qB0 + x1B[3 * u + 1] * qB1 + x1B[3 * u + 2] * qB2;
                colfma8_2(mA, mB, WK + (384 + u * 8 + w) * 4, pk2(gA), pk2(gB));
            }
        }
    }
    // finalize
    ull hk[8];
    table_lerp(g_tk, dA, hk);
    float2 sA2 = upk(dot8p(hk, mA));
    table_lerp(g_tk, dB, hk);
    float2 sB2 = upk(dot8p(hk, mB));
    float scoreA = (sA2.x + sA2.y) * 0.0028527222f;
    float scoreB = (sB2.x + sB2.y) * 0.0028527222f;
    float tcA = 10.0f * (1.0f - dA * 0.125f);
    float tcB = 10.0f * (1.0f - dB * 0.125f);
    float cutA = (tcA > 0.f) ? __expf(-__frcp_rn(tcA)) : 0.f;
    float cutB = (tcB > 0.f) ? __expf(-__frcp_rn(tcB)) : 0.f;
    float evA = cutA * __expf(scoreA);
    float evB = cutB * __expf(scoreB);
    if (v0) { g_expv[e0] = evA; atomicAdd(&g_z[dstA], evA); }
    if (v1) { g_expv[e1] = evB; atomicAdd(&g_z[dstB], evB); }
}

// -------- value kernel: TWO edges per thread (dst-sorted)
__global__ __launch_bounds__(128) void edge_value(
    const float* __restrict__ x, float* __restrict__ out, int E) {
    __shared__ __align__(16) float Wv[9216];
    {
        float4* s4 = reinterpret_cast<float4*>(Wv);
        const float4* g4 = reinterpret_cast<const float4*>(g_WvT);
        for (int i = threadIdx.x; i < 2304; i += 128) s4[i] = g4[i];
    }
    __syncthreads();
    const ulonglong2* WV = reinterpret_cast<const ulonglong2*>(Wv);

    int e0 = blockIdx.x * 256 + threadIdx.x;
    int e1 = e0 + 128;
    bool v0 = e0 < E, v1 = e1 < E;
    int ia = v0 ? e0 : 0, ib = v1 ? e1 : 0;
    int srcA = g_src[ia], dstA = g_dst[ia];
    int srcB = g_src[ib], dstB = g_dst[ib];
    const float4 shA = g_sea[ia];
    const float4 shB = g_sea[ib];
    float dA = g_sd[ia], dB = g_sd[ib];

    float fsA = sqrtf(g_expv[ia]) * 0.0510310363f;
    float fsB = sqrtf(g_expv[ib]) * 0.0510310363f;

    ull hvA[8], hvB[8];
    table_lerp(g_tv, dA, hvA);
    table_lerp(g_tv, dB, hvB);

    float x0A[16], x0B[16];
    ld16(x0A, x + srcA * 40); ld16(x0B, x + srcB * 40);

    // A-phase: A[w] = hv . (sum_u x0[u] W2col(u,w)), cols 256+u*8+w
    float AA[8], AB[8];
    #pragma unroll 1
    for (int w = 0; w < 8; ++w) {
        ull UA[8], UB[8];
        #pragma unroll
        for (int i = 0; i < 8; ++i) { UA[i] = pk2(0.f); UB[i] = pk2(0.f); }
        #pragma unroll
        for (int u = 0; u < 16; ++u)
            colfma8_2(UA, UB, WV + (256 + u * 8 + w) * 4, pk2(x0A[u]), pk2(x0B[u]));
        float2 tA = upk(dot8p(hvA, UA)); AA[w] = tA.x + tA.y;
        float2 tB = upk(dot8p(hvB, UB)); AB[w] = tB.x + tB.y;
    }
    // dd (x1 streamed)
    float ddA[8], ddB[8];
    {
        float tA[24], tB[24];
        ld24(tA, x + srcA * 40 + 16); ld24(tB, x + srcB * 40 + 16);
        #pragma unroll
        for (int u = 0; u < 8; ++u) {
            ddA[u] = (tA[3 * u] * shA.y + tA[3 * u + 1] * shA.z + tA[3 * u + 2] * shA.w) * 0.57735027f;
            ddB[u] = (tB[3 * u] * shB.y + tB[3 * u + 1] * shB.z + tB[3 * u + 2] * shB.w) * 0.57735027f;
        }
    }
    float* obA = out + dstA * 40;
    float* obB = out + dstB * 40;

    // o0: scale x0 in place to a0 = x0*sh0; per w: U over block1(16,a0) + block4(8,dd)
    #pragma unroll
    for (int u = 0; u < 16; ++u) { x0A[u] *= shA.x; x0B[u] *= shB.x; }
    #pragma unroll 1
    for (int w = 0; w < 16; ++w) {
        ull UA[8], UB[8];
        #pragma unroll
        for (int i = 0; i < 8; ++i) { UA[i] = pk2(0.f); UB[i] = pk2(0.f); }
        #pragma unroll
        for (int u = 0; u < 16; ++u)
            colfma8_2(UA, UB, WV + (u * 16 + w) * 4, pk2(x0A[u]), pk2(x0B[u]));
        #pragma unroll
        for (int u = 0; u < 8; ++u)
            colfma8_2(UA, UB, WV + (448 + u * 16 + w) * 4, pk2(ddA[u]), pk2(ddB[u]));
        float2 sA = upk(dot8p(hvA, UA));
        float2 sB = upk(dot8p(hvB, UB));
        if (v0) atomicAdd(obA + w, (sA.x + sA.y) * fsA);
        if (v1) atomicAdd(obB + w, (sB.x + sB.y) * fsB);
    }
    // o1: x1s resident; per w: vxyz = A[w]*sh1 + sum_u (hv.W3col)*x1s[u,:]
    float x1A[24], x1B[24];
    ld24(x1A, x + srcA * 40 + 16); ld24(x1B, x + srcB * 40 + 16);
    #pragma unroll
    for (int k = 0; k < 24; ++k) { x1A[k] *= shA.x; x1B[k] *= shB.x; }
    #pragma unroll 1
    for (int w = 0; w < 8; ++w) {
        float vxA = AA[w] * shA.y, vyA = AA[w] * shA.z, vzA = AA[w] * shA.w;
        float vxB = AB[w] * shB.y, vyB = AB[w] * shB.z, vzB = AB[w] * shB.w;
        #pragma unroll
        for (int u = 0; u < 8; ++u) {
            float sA_, sB_;
            coldot2(hvA, hvB, WV + (384 + u * 8 + w) * 4, sA_, sB_);
            vxA = fmaf(sA_, x1A[3 * u], vxA);
            vyA = fmaf(sA_, x1A[3 * u + 1], vyA);
            vzA = fmaf(sA_, x1A[3 * u + 2], vzA);
            vxB = fmaf(sB_, x1B[3 * u], vxB);
            vyB = fmaf(sB_, x1B[3 * u + 1], vyB);
            vzB = fmaf(sB_, x1B[3 * u + 2], vzB);
        }
        if (v0) {
            atomicAdd(obA + 16 + 3 * w, vxA * fsA);
            atomicAdd(obA + 17 + 3 * w, vyA * fsA);
            atomicAdd(obA + 18 + 3 * w, vzA * fsA);
        }
        if (v1) {
            atomicAdd(obB + 16 + 3 * w, vxB * fsB);
            atomicAdd(obB + 17 + 3 * w, vyB * fsB);
            atomicAdd(obB + 18 + 3 * w, vzB * fsB);
        }
    }
}

// -------- epilogue: out[i] *= rsqrt(z[i])
__global__ void normalize(float* __restrict__ out, int n) {
    int i = blockIdx.x * 128 + threadIdx.x;
    if (i >= n) return;
    float zz = g_z[i];
    if (zz <= 0.f) zz = 1.f;
    float s = rsqrtf(zz);
    float4* o4 = reinterpret_cast<float4*>(out + i * 40);
    #pragma unroll
    for (int m = 0; m < 10; ++m) {
        float4 v = o4[m];
        v.x *= s; v.y *= s; v.z *= s; v.w *= s;
        o4[m] = v;
    }
}

extern "C" void kernel_launch(void* const* d_in, const int* in_sizes, int n_in,
                              void* d_out, int out_size) {
    const float* x   = (const float*)d_in[0];
    const int*   ei  = (const int*)d_in[1];
    const float* ea  = (const float*)d_in[2];
    const float* amf = (const float*)d_in[5];
    const float* Wq0 = (const float*)d_in[6];
    const float* Wq1 = (const float*)d_in[7];
    const float* Wk1 = (const float*)d_in[8];
    const float* Wk2 = (const float*)d_in[9];
    const float* Wv1 = (const float*)d_in[10];
    const float* Wv2 = (const float*)d_in[11];
    const float* Wd0 = (const float*)d_in[12];
    const float* Wd1 = (const float*)d_in[13];
    float* out = (float*)d_out;

    int n = in_sizes[0] / 40;
    int E = in_sizes[2] / 4;

    setup_kernel<<<(18432 + TBL + NMAX + 255) / 256, 256>>>(Wk2, Wv2, Wk1, Wv1);
    hist_kernel<<<(E + 255) / 256, 256>>>(ei, E);
    scan_kernel<<<1, 1024>>>(n);
    scatter_kernel<<<(E + 255) / 256, 256>>>(ei, ea, amf, E);
    node_prep<<<(n + 127) / 128, 128>>>(x, Wq0, Wq1, Wd0, Wd1, out, n);
    int grid = (E + 255) / 256;
    edge_score<<<grid, 128>>>(x, E);
    edge_value<<<grid, 128>>>(x, out, E);
    normalize<<<(n + 127) / 128, 128>>>(out, n);
}